// round 1
// baseline (speedup 1.0000x reference)
#include <cuda_runtime.h>
#include <cstdint>
#include <math.h>

#define B_  4
#define S_  2048
#define H_  1024
#define NH_ 16
#define HD_ 64

// Scratch for projected Q/K/V in head-split layout [B, NH, S, HD] (fp32).
__device__ float g_q[B_ * NH_ * S_ * HD_];
__device__ float g_k[B_ * NH_ * S_ * HD_];
__device__ float g_v[B_ * NH_ * S_ * HD_];

__device__ __forceinline__ unsigned f2tf(float x) {
    unsigned r;
    asm("cvt.rna.tf32.f32 %0, %1;" : "=r"(r) : "f"(x));
    return r;
}

__device__ __forceinline__ void mma8(float* c, const unsigned* a, const unsigned* b) {
    asm volatile(
        "mma.sync.aligned.m16n8k8.row.col.f32.tf32.tf32.f32 "
        "{%0,%1,%2,%3}, {%4,%5,%6,%7}, {%8,%9}, {%0,%1,%2,%3};\n"
        : "+f"(c[0]), "+f"(c[1]), "+f"(c[2]), "+f"(c[3])
        : "r"(a[0]), "r"(a[1]), "r"(a[2]), "r"(a[3]), "r"(b[0]), "r"(b[1]));
}

// ---------------------------------------------------------------------------
// Kernel 1: fused QKV projection.
//   C[8192, 3072] = hidden[8192,1024] @ [Wq|Wk|Wv] + bias + emb[index]
//   written head-split into g_q/g_k/g_v.
// Block tile: BM=128, BN=64, BK=32. 256 threads = 8 warps (4x2 warp grid,
// each warp computes 32x32 via 2x4 m16n8k8 tf32 mmas).
// ---------------------------------------------------------------------------
__global__ __launch_bounds__(256) void qkv_proj(
    const float* __restrict__ hs,
    const float* __restrict__ Wq, const float* __restrict__ bq,
    const float* __restrict__ Wk, const float* __restrict__ bk,
    const float* __restrict__ Wv, const float* __restrict__ bv,
    const float* __restrict__ qe, const float* __restrict__ ke,
    const float* __restrict__ ve,
    const int* __restrict__ indexp)
{
    // Strides chosen so fragment-read bank = (4*g + t + const) % 32: conflict-free.
    __shared__ unsigned As[128][36];  // A tile, [row][k], stride 36 (== 4 mod 32)
    __shared__ unsigned Bs[32][68];   // B tile, [k][col], stride 68 (== 4 mod 32)

    const int tid  = threadIdx.x;
    const int lane = tid & 31;
    const int wid  = tid >> 5;
    const int g    = lane >> 2;   // groupID (row within fragment)
    const int t    = lane & 3;    // threadID-in-group
    const int wm   = wid & 3;     // warp row  (0..3) -> 32 rows each
    const int wn   = wid >> 2;    // warp col  (0..1) -> 32 cols each

    const int nb   = blockIdx.x;  // 0..47 (16 n-blocks per matrix)
    const int mb   = blockIdx.y;  // 0..63
    const int sel  = nb >> 4;     // 0=Q, 1=K, 2=V

    const float* W    = sel == 0 ? Wq : (sel == 1 ? Wk : Wv);
    const float* bias = sel == 0 ? bq : (sel == 1 ? bk : bv);
    const float* emb  = (sel == 0 ? qe : (sel == 1 ? ke : ve)) + indexp[0] * H_;
    float* buf        = sel == 0 ? g_q : (sel == 1 ? g_k : g_v);

    const int colm = (nb & 15) * 64;  // column base within the 1024-wide matrix
    const int row0 = mb * 128;

    float acc[2][4][4] = {};

    for (int kt = 0; kt < H_; kt += 32) {
        // Load A tile: 128x32 floats = 1024 float4, 4 per thread.
        #pragma unroll
        for (int i = 0; i < 4; i++) {
            int idx = tid + i * 256;
            int r = idx >> 3, c4 = (idx & 7) * 4;
            float4 v = *(const float4*)&hs[(size_t)(row0 + r) * H_ + kt + c4];
            uint4 u = make_uint4(f2tf(v.x), f2tf(v.y), f2tf(v.z), f2tf(v.w));
            *(uint4*)&As[r][c4] = u;
        }
        // Load B tile: 32x64 floats = 512 float4, 2 per thread.
        #pragma unroll
        for (int i = 0; i < 2; i++) {
            int idx = tid + i * 256;
            int r = idx >> 4, c4 = (idx & 15) * 4;
            float4 v = *(const float4*)&W[(size_t)(kt + r) * H_ + colm + c4];
            uint4 u = make_uint4(f2tf(v.x), f2tf(v.y), f2tf(v.z), f2tf(v.w));
            *(uint4*)&Bs[r][c4] = u;
        }
        __syncthreads();

        #pragma unroll
        for (int kk = 0; kk < 4; kk++) {  // 4 k-steps of 8
            unsigned a[2][4];
            #pragma unroll
            for (int mt = 0; mt < 2; mt++) {
                int r = wm * 32 + mt * 16;
                a[mt][0] = As[r + g    ][kk * 8 + t    ];
                a[mt][1] = As[r + g + 8][kk * 8 + t    ];
                a[mt][2] = As[r + g    ][kk * 8 + t + 4];
                a[mt][3] = As[r + g + 8][kk * 8 + t + 4];
            }
            #pragma unroll
            for (int nt = 0; nt < 4; nt++) {
                unsigned b[2];
                int c = wn * 32 + nt * 8 + g;
                b[0] = Bs[kk * 8 + t    ][c];
                b[1] = Bs[kk * 8 + t + 4][c];
                mma8(acc[0][nt], a[0], b);
                mma8(acc[1][nt], a[1], b);
            }
        }
        __syncthreads();
    }

    // Epilogue: + bias + emb, scatter to head-split layout.
    #pragma unroll
    for (int nt = 0; nt < 4; nt++) {
        const int cm   = colm + wn * 32 + nt * 8 + 2 * t;
        const float b0 = bias[cm]     + emb[cm];
        const float b1 = bias[cm + 1] + emb[cm + 1];
        const int head = cm >> 6;
        const int d    = cm & 63;
        #pragma unroll
        for (int mt = 0; mt < 2; mt++) {
            int row = row0 + wm * 32 + mt * 16 + g;
            int bb  = row >> 11;       // batch
            int s   = row & 2047;      // seq pos
            size_t base = ((size_t)(bb * NH_ + head) * S_ + s) * HD_ + d;
            *(float2*)&buf[base] =
                make_float2(acc[mt][nt][0] + b0, acc[mt][nt][1] + b1);
            *(float2*)&buf[base + 8 * HD_] =
                make_float2(acc[mt][nt][2] + b0, acc[mt][nt][3] + b1);
        }
    }
}

// ---------------------------------------------------------------------------
// Kernel 2: flash attention (tf32 mma), online softmax.
// Block: one (b,h) x 64 q-rows. 4 warps, each owns 16 q-rows.
// K/V tiles of 64 keys staged in smem (tf32). P re-layout via dead Ks region.
// ---------------------------------------------------------------------------
__global__ __launch_bounds__(128) void flash_attn(
    const float* __restrict__ mask, float* __restrict__ out)
{
    __shared__ unsigned Ks[64][68];  // K tile (then reused for P)
    __shared__ unsigned Vs[64][68];  // V tile
    __shared__ float    Ms[64];      // mask tile

    const int tid  = threadIdx.x;
    const int lane = tid & 31;
    const int wid  = tid >> 5;
    const int g    = lane >> 2;
    const int t    = lane & 3;

    const int bh = blockIdx.y;       // 0..63
    const int b  = bh >> 4, h = bh & 15;
    const float* Qp = g_q + (size_t)bh * S_ * HD_;
    const float* Kp = g_k + (size_t)bh * S_ * HD_;
    const float* Vp = g_v + (size_t)bh * S_ * HD_;
    const int q0 = blockIdx.x * 64 + wid * 16;

    // Q fragments (scale 1/sqrt(64) folded in), resident for the whole block.
    unsigned qa[8][4];
    #pragma unroll
    for (int dc = 0; dc < 8; dc++) {
        qa[dc][0] = f2tf(Qp[(size_t)(q0 + g    ) * HD_ + dc * 8 + t    ] * 0.125f);
        qa[dc][1] = f2tf(Qp[(size_t)(q0 + g + 8) * HD_ + dc * 8 + t    ] * 0.125f);
        qa[dc][2] = f2tf(Qp[(size_t)(q0 + g    ) * HD_ + dc * 8 + t + 4] * 0.125f);
        qa[dc][3] = f2tf(Qp[(size_t)(q0 + g + 8) * HD_ + dc * 8 + t + 4] * 0.125f);
    }

    float o[8][4] = {};
    float mr0 = -1e30f, mr1 = -1e30f, lr0 = 0.f, lr1 = 0.f;

    for (int kt = 0; kt < S_; kt += 64) {
        __syncthreads();  // previous iteration's smem reads complete

        // Stage K, V tiles (64x64 each) as tf32.
        #pragma unroll
        for (int i = 0; i < 8; i++) {
            int idx = tid + i * 128;
            int r = idx >> 4, c4 = (idx & 15) * 4;
            float4 kv = *(const float4*)&Kp[(size_t)(kt + r) * HD_ + c4];
            *(uint4*)&Ks[r][c4] =
                make_uint4(f2tf(kv.x), f2tf(kv.y), f2tf(kv.z), f2tf(kv.w));
            float4 vv = *(const float4*)&Vp[(size_t)(kt + r) * HD_ + c4];
            *(uint4*)&Vs[r][c4] =
                make_uint4(f2tf(vv.x), f2tf(vv.y), f2tf(vv.z), f2tf(vv.w));
        }
        if (tid < 16)
            *(float4*)&Ms[tid * 4] = *(const float4*)&mask[b * S_ + kt + tid * 4];
        __syncthreads();

        // S = Q @ K^T  (16 q-rows x 64 keys per warp)
        float s[8][4] = {};
        #pragma unroll
        for (int dc = 0; dc < 8; dc++) {
            #pragma unroll
            for (int nt = 0; nt < 8; nt++) {
                unsigned bb[2] = { Ks[nt * 8 + g][dc * 8 + t],
                                   Ks[nt * 8 + g][dc * 8 + t + 4] };
                mma8(s[nt], qa[dc], bb);
            }
        }

        // mask + row max
        float r0 = -1e30f, r1 = -1e30f;
        #pragma unroll
        for (int nt = 0; nt < 8; nt++) {
            float m0 = Ms[nt * 8 + 2 * t], m1 = Ms[nt * 8 + 2 * t + 1];
            s[nt][0] += m0; s[nt][1] += m1; s[nt][2] += m0; s[nt][3] += m1;
            r0 = fmaxf(r0, fmaxf(s[nt][0], s[nt][1]));
            r1 = fmaxf(r1, fmaxf(s[nt][2], s[nt][3]));
        }
        r0 = fmaxf(r0, __shfl_xor_sync(0xffffffffu, r0, 1));
        r0 = fmaxf(r0, __shfl_xor_sync(0xffffffffu, r0, 2));
        r1 = fmaxf(r1, __shfl_xor_sync(0xffffffffu, r1, 1));
        r1 = fmaxf(r1, __shfl_xor_sync(0xffffffffu, r1, 2));

        float mn0 = fmaxf(mr0, r0), mn1 = fmaxf(mr1, r1);
        float al0 = __expf(mr0 - mn0), al1 = __expf(mr1 - mn1);
        mr0 = mn0; mr1 = mn1;

        // P = exp(S - m), row sums
        float ps0 = 0.f, ps1 = 0.f;
        #pragma unroll
        for (int nt = 0; nt < 8; nt++) {
            s[nt][0] = __expf(s[nt][0] - mn0);
            s[nt][1] = __expf(s[nt][1] - mn0);
            s[nt][2] = __expf(s[nt][2] - mn1);
            s[nt][3] = __expf(s[nt][3] - mn1);
            ps0 += s[nt][0] + s[nt][1];
            ps1 += s[nt][2] + s[nt][3];
        }
        ps0 += __shfl_xor_sync(0xffffffffu, ps0, 1);
        ps0 += __shfl_xor_sync(0xffffffffu, ps0, 2);
        ps1 += __shfl_xor_sync(0xffffffffu, ps1, 1);
        ps1 += __shfl_xor_sync(0xffffffffu, ps1, 2);
        lr0 = lr0 * al0 + ps0;
        lr1 = lr1 * al1 + ps1;

        // Re-layout P (C-frag -> A-frag) through the now-dead Ks region.
        __syncthreads();  // all warps finished reading Ks
        const int pr = wid * 16;
        #pragma unroll
        for (int nt = 0; nt < 8; nt++) {
            Ks[pr + g    ][nt * 8 + 2 * t    ] = f2tf(s[nt][0]);
            Ks[pr + g    ][nt * 8 + 2 * t + 1] = f2tf(s[nt][1]);
            Ks[pr + g + 8][nt * 8 + 2 * t    ] = f2tf(s[nt][2]);
            Ks[pr + g + 8][nt * 8 + 2 * t + 1] = f2tf(s[nt][3]);
        }
        __syncwarp();

        // O = O*alpha + P @ V
        #pragma unroll
        for (int dt = 0; dt < 8; dt++) {
            o[dt][0] *= al0; o[dt][1] *= al0;
            o[dt][2] *= al1; o[dt][3] *= al1;
        }
        #pragma unroll
        for (int kc = 0; kc < 8; kc++) {
            unsigned a[4] = { Ks[pr + g    ][kc * 8 + t    ],
                              Ks[pr + g + 8][kc * 8 + t    ],
                              Ks[pr + g    ][kc * 8 + t + 4],
                              Ks[pr + g + 8][kc * 8 + t + 4] };
            #pragma unroll
            for (int dt = 0; dt < 8; dt++) {
                unsigned bb[2] = { Vs[kc * 8 + t    ][dt * 8 + g],
                                   Vs[kc * 8 + t + 4][dt * 8 + g] };
                mma8(o[dt], a, bb);
            }
        }
    }

    // Normalize and write ctx in [B, S, NH*HD] layout.
    const float i0 = 1.0f / lr0, i1 = 1.0f / lr1;
    #pragma unroll
    for (int dt = 0; dt < 8; dt++) {
        size_t base = (size_t)(b * S_ + q0 + g) * H_ + h * HD_ + dt * 8 + 2 * t;
        *(float2*)&out[base] = make_float2(o[dt][0] * i0, o[dt][1] * i0);
        *(float2*)&out[base + 8 * (size_t)H_] =
            make_float2(o[dt][2] * i1, o[dt][3] * i1);
    }
}

// ---------------------------------------------------------------------------
extern "C" void kernel_launch(void* const* d_in, const int* in_sizes, int n_in,
                              void* d_out, int out_size)
{
    const float* hs   = (const float*)d_in[0];
    const float* mask = (const float*)d_in[1];
    const float* Wq   = (const float*)d_in[2];
    const float* bq   = (const float*)d_in[3];
    const float* Wk   = (const float*)d_in[4];
    const float* bk   = (const float*)d_in[5];
    const float* Wv   = (const float*)d_in[6];
    const float* bv   = (const float*)d_in[7];
    const float* qe   = (const float*)d_in[8];
    const float* ke   = (const float*)d_in[9];
    const float* ve   = (const float*)d_in[10];
    const int*   idx  = (const int*)d_in[11];

    dim3 g1(48, 64);           // 48 n-blocks (3*1024/64) x 64 m-blocks (8192/128)
    qkv_proj<<<g1, 256>>>(hs, Wq, bq, Wk, bk, Wv, bv, qe, ke, ve, idx);

    dim3 g2(S_ / 64, B_ * NH_);  // 32 q-tiles x 64 (b,h) pairs
    flash_attn<<<g2, 128>>>(mask, (float*)d_out);
}

// round 3
// speedup vs baseline: 1.5891x; 1.5891x over previous
#include <cuda_runtime.h>
#include <cstdint>
#include <math.h>

#define B_  4
#define S_  2048
#define H_  1024
#define NH_ 16
#define HD_ 64

// Scratch for projected Q/K/V, head-split [B, NH, S, HD], stored as tf32 bit
// patterns (Q pre-scaled by 1/sqrt(HD)).
__device__ float g_q[B_ * NH_ * S_ * HD_];
__device__ float g_k[B_ * NH_ * S_ * HD_];
__device__ float g_v[B_ * NH_ * S_ * HD_];

__device__ __forceinline__ unsigned f2tf(float x) {
    unsigned r;
    asm("cvt.rna.tf32.f32 %0, %1;" : "=r"(r) : "f"(x));
    return r;
}

__device__ __forceinline__ void mma8(float* c, const unsigned* a, const unsigned* b) {
    asm volatile(
        "mma.sync.aligned.m16n8k8.row.col.f32.tf32.tf32.f32 "
        "{%0,%1,%2,%3}, {%4,%5,%6,%7}, {%8,%9}, {%0,%1,%2,%3};\n"
        : "+f"(c[0]), "+f"(c[1]), "+f"(c[2]), "+f"(c[3])
        : "r"(a[0]), "r"(a[1]), "r"(a[2]), "r"(a[3]), "r"(b[0]), "r"(b[1]));
}

__device__ __forceinline__ void cpa16(void* dst, const void* src) {
    unsigned d = (unsigned)__cvta_generic_to_shared(dst);
    asm volatile("cp.async.cg.shared.global [%0], [%1], 16;\n" :: "r"(d), "l"(src));
}
#define CP_COMMIT asm volatile("cp.async.commit_group;\n" ::: "memory")
#define CP_WAIT1  asm volatile("cp.async.wait_group 1;\n" ::: "memory")

// ---------------------------------------------------------------------------
// Kernel 1: fused QKV projection, cp.async double-buffered.
//   BM=128, BN=128, BK=32. 256 threads = 8 warps (4m x 2n), warp tile 32x64.
//   Epilogue: +bias +emb, tf32-convert (Q also * 1/8), head-split scatter.
// ---------------------------------------------------------------------------
#define AS_ST 36   // 36 mod 32 = 4  -> a-frag bank = 4g+t  (conflict-free)
#define BS_ST 136  // 136 mod 32 = 8 -> b-frag bank = 8t+g  (conflict-free)
#define QKV_SMEM ((2*128*AS_ST + 2*32*BS_ST) * 4)

__global__ __launch_bounds__(256, 2) void qkv_proj(
    const float* __restrict__ hs,
    const float* __restrict__ Wq, const float* __restrict__ bq,
    const float* __restrict__ Wk, const float* __restrict__ bk,
    const float* __restrict__ Wv, const float* __restrict__ bv,
    const float* __restrict__ qe, const float* __restrict__ ke,
    const float* __restrict__ ve,
    const int* __restrict__ indexp)
{
    extern __shared__ float qsm[];
    float* As = qsm;                    // [2][128][AS_ST]
    float* Bs = qsm + 2 * 128 * AS_ST;  // [2][32][BS_ST]
#define AT(bf,r,c) As[(bf)*128*AS_ST + (r)*AS_ST + (c)]
#define BT(bf,r,c) Bs[(bf)*32*BS_ST + (r)*BS_ST + (c)]

    const int tid  = threadIdx.x;
    const int lane = tid & 31;
    const int wid  = tid >> 5;
    const int g    = lane >> 2;
    const int t    = lane & 3;
    const int wm   = wid & 3;    // 4 m-warps, 32 rows each
    const int wn   = wid >> 2;   // 2 n-warps, 64 cols each

    const int nb   = blockIdx.x;  // 0..23 (8 per matrix)
    const int mb   = blockIdx.y;  // 0..63
    const int sel  = nb >> 3;     // 0=Q, 1=K, 2=V

    const float* W    = sel == 0 ? Wq : (sel == 1 ? Wk : Wv);
    const float* bias = sel == 0 ? bq : (sel == 1 ? bk : bv);
    const float* emb  = (sel == 0 ? qe : (sel == 1 ? ke : ve)) + indexp[0] * H_;
    float* buf        = sel == 0 ? g_q : (sel == 1 ? g_k : g_v);
    const float sc    = sel == 0 ? 0.125f : 1.0f;

    const int colm = (nb & 7) * 128;
    const int row0 = mb * 128;

    float acc[2][8][4] = {};

    auto stage = [&](int kt, int bf) {
        #pragma unroll
        for (int i = 0; i < 4; i++) {
            int idx = tid + i * 256;
            int r = idx >> 3, c4 = (idx & 7) * 4;
            cpa16(&AT(bf, r, c4), &hs[(size_t)(row0 + r) * H_ + kt + c4]);
        }
        #pragma unroll
        for (int i = 0; i < 4; i++) {
            int idx = tid + i * 256;
            int r = idx >> 5, c4 = (idx & 31) * 4;
            cpa16(&BT(bf, r, c4), &W[(size_t)(kt + r) * H_ + colm + c4]);
        }
    };

    stage(0, 0);
    CP_COMMIT;

    for (int it = 0; it < H_ / 32; it++) {
        const int bf = it & 1;
        if (it + 1 < H_ / 32) stage((it + 1) * 32, bf ^ 1);
        CP_COMMIT;
        CP_WAIT1;
        __syncthreads();

        #pragma unroll
        for (int kk = 0; kk < 4; kk++) {
            unsigned a[2][4];
            #pragma unroll
            for (int mt = 0; mt < 2; mt++) {
                int r = wm * 32 + mt * 16;
                a[mt][0] = f2tf(AT(bf, r + g,     kk * 8 + t));
                a[mt][1] = f2tf(AT(bf, r + g + 8, kk * 8 + t));
                a[mt][2] = f2tf(AT(bf, r + g,     kk * 8 + t + 4));
                a[mt][3] = f2tf(AT(bf, r + g + 8, kk * 8 + t + 4));
            }
            #pragma unroll
            for (int nt = 0; nt < 8; nt++) {
                int c = wn * 64 + nt * 8 + g;
                unsigned bb[2] = { f2tf(BT(bf, kk * 8 + t,     c)),
                                   f2tf(BT(bf, kk * 8 + t + 4, c)) };
                mma8(acc[0][nt], a[0], bb);
                mma8(acc[1][nt], a[1], bb);
            }
        }
        __syncthreads();
    }

    // Epilogue: +bias+emb, scale (Q), tf32 bits, head-split scatter.
    #pragma unroll
    for (int nt = 0; nt < 8; nt++) {
        const int cm   = colm + wn * 64 + nt * 8 + 2 * t;
        const float b0 = bias[cm]     + emb[cm];
        const float b1 = bias[cm + 1] + emb[cm + 1];
        const int head = cm >> 6;
        const int d    = cm & 63;
        #pragma unroll
        for (int mt = 0; mt < 2; mt++) {
            int row = row0 + wm * 32 + mt * 16 + g;
            int bb  = row >> 11;
            int s   = row & 2047;
            size_t base = ((size_t)(bb * NH_ + head) * S_ + s) * HD_ + d;
            uint2 u0 = make_uint2(f2tf((acc[mt][nt][0] + b0) * sc),
                                  f2tf((acc[mt][nt][1] + b1) * sc));
            uint2 u1 = make_uint2(f2tf((acc[mt][nt][2] + b0) * sc),
                                  f2tf((acc[mt][nt][3] + b1) * sc));
            *(uint2*)&buf[base]            = u0;
            *(uint2*)&buf[base + 8 * HD_]  = u1;
        }
    }
#undef AT
#undef BT
}

// ---------------------------------------------------------------------------
// Kernel 2: flash attention, cp.async double-buffered K/V/mask.
//   Block = 128 q-rows x one (b,h). 8 warps, warp owns 16 q-rows.
// ---------------------------------------------------------------------------
#define KS_ST 68   // QK b-frag bank = 4g+t (conflict-free)
#define VS_ST 72   // PV b-frag bank = 8t+g (conflict-free)
#define PS_ST 72
#define FL_SMEM ((2*64*KS_ST + 2*64*VS_ST + 128*PS_ST + 2*64) * 4)

__global__ __launch_bounds__(256, 1) void flash_attn(
    const float* __restrict__ mask, float* __restrict__ out)
{
    extern __shared__ unsigned fsm[];
    unsigned* Ks = fsm;                         // [2][64][KS_ST]
    unsigned* Vs = Ks + 2 * 64 * KS_ST;         // [2][64][VS_ST]
    unsigned* Ps = Vs + 2 * 64 * VS_ST;         // [128][PS_ST]
    float*    Ms = (float*)(Ps + 128 * PS_ST);  // [2][64]
#define KT(bf,r,c) Ks[(bf)*64*KS_ST + (r)*KS_ST + (c)]
#define VT(bf,r,c) Vs[(bf)*64*VS_ST + (r)*VS_ST + (c)]
#define PT(r,c)    Ps[(r)*PS_ST + (c)]

    const int tid  = threadIdx.x;
    const int lane = tid & 31;
    const int wid  = tid >> 5;
    const int g    = lane >> 2;
    const int t    = lane & 3;

    const int bh = blockIdx.y;
    const int b  = bh >> 4, h = bh & 15;
    const float* Qp = g_q + (size_t)bh * S_ * HD_;
    const float* Kp = g_k + (size_t)bh * S_ * HD_;
    const float* Vp = g_v + (size_t)bh * S_ * HD_;
    const float* maskp = mask + b * S_;
    const int q0 = blockIdx.x * 128 + wid * 16;

    auto stage = [&](int kt, int bf) {
        #pragma unroll
        for (int i = 0; i < 4; i++) {
            int idx = tid + i * 256;
            int r = idx >> 4, c4 = (idx & 15) * 4;
            cpa16(&KT(bf, r, c4), &Kp[(size_t)(kt + r) * HD_ + c4]);
            cpa16(&VT(bf, r, c4), &Vp[(size_t)(kt + r) * HD_ + c4]);
        }
        if (tid < 16) cpa16(&Ms[bf * 64 + tid * 4], &maskp[kt + tid * 4]);
    };

    // Q fragments (already tf32 + pre-scaled), resident for the whole block.
    unsigned qa[8][4];
    #pragma unroll
    for (int dc = 0; dc < 8; dc++) {
        qa[dc][0] = __float_as_uint(Qp[(size_t)(q0 + g    ) * HD_ + dc * 8 + t]);
        qa[dc][1] = __float_as_uint(Qp[(size_t)(q0 + g + 8) * HD_ + dc * 8 + t]);
        qa[dc][2] = __float_as_uint(Qp[(size_t)(q0 + g    ) * HD_ + dc * 8 + t + 4]);
        qa[dc][3] = __float_as_uint(Qp[(size_t)(q0 + g + 8) * HD_ + dc * 8 + t + 4]);
    }

    float o[8][4] = {};
    float mr0 = -1e30f, mr1 = -1e30f, lr0 = 0.f, lr1 = 0.f;

    stage(0, 0);
    CP_COMMIT;

    for (int it = 0; it < S_ / 64; it++) {
        const int bf = it & 1;
        if (it + 1 < S_ / 64) stage((it + 1) * 64, bf ^ 1);
        CP_COMMIT;
        CP_WAIT1;
        __syncthreads();

        // S = Q @ K^T
        float s[8][4] = {};
        #pragma unroll
        for (int dc = 0; dc < 8; dc++) {
            #pragma unroll
            for (int nt = 0; nt < 8; nt++) {
                unsigned bb[2] = { KT(bf, nt * 8 + g, dc * 8 + t),
                                   KT(bf, nt * 8 + g, dc * 8 + t + 4) };
                mma8(s[nt], qa[dc], bb);
            }
        }

        // mask + row max
        float r0 = -1e30f, r1 = -1e30f;
        #pragma unroll
        for (int nt = 0; nt < 8; nt++) {
            float m0 = Ms[bf * 64 + nt * 8 + 2 * t];
            float m1 = Ms[bf * 64 + nt * 8 + 2 * t + 1];
            s[nt][0] += m0; s[nt][1] += m1; s[nt][2] += m0; s[nt][3] += m1;
            r0 = fmaxf(r0, fmaxf(s[nt][0], s[nt][1]));
            r1 = fmaxf(r1, fmaxf(s[nt][2], s[nt][3]));
        }
        r0 = fmaxf(r0, __shfl_xor_sync(0xffffffffu, r0, 1));
        r0 = fmaxf(r0, __shfl_xor_sync(0xffffffffu, r0, 2));
        r1 = fmaxf(r1, __shfl_xor_sync(0xffffffffu, r1, 1));
        r1 = fmaxf(r1, __shfl_xor_sync(0xffffffffu, r1, 2));

        float mn0 = fmaxf(mr0, r0), mn1 = fmaxf(mr1, r1);
        float al0 = __expf(mr0 - mn0), al1 = __expf(mr1 - mn1);
        mr0 = mn0; mr1 = mn1;

        // P = exp(S - m), row sums
        float ps0 = 0.f, ps1 = 0.f;
        #pragma unroll
        for (int nt = 0; nt < 8; nt++) {
            s[nt][0] = __expf(s[nt][0] - mn0);
            s[nt][1] = __expf(s[nt][1] - mn0);
            s[nt][2] = __expf(s[nt][2] - mn1);
            s[nt][3] = __expf(s[nt][3] - mn1);
            ps0 += s[nt][0] + s[nt][1];
            ps1 += s[nt][2] + s[nt][3];
        }
        ps0 += __shfl_xor_sync(0xffffffffu, ps0, 1);
        ps0 += __shfl_xor_sync(0xffffffffu, ps0, 2);
        ps1 += __shfl_xor_sync(0xffffffffu, ps1, 1);
        ps1 += __shfl_xor_sync(0xffffffffu, ps1, 2);
        lr0 = lr0 * al0 + ps0;
        lr1 = lr1 * al1 + ps1;

        // Re-layout P (C-frag -> A-frag) via warp-private smem slice.
        const int pr = wid * 16;
        #pragma unroll
        for (int nt = 0; nt < 8; nt++) {
            PT(pr + g,     nt * 8 + 2 * t    ) = f2tf(s[nt][0]);
            PT(pr + g,     nt * 8 + 2 * t + 1) = f2tf(s[nt][1]);
            PT(pr + g + 8, nt * 8 + 2 * t    ) = f2tf(s[nt][2]);
            PT(pr + g + 8, nt * 8 + 2 * t + 1) = f2tf(s[nt][3]);
        }
        __syncwarp();

        // O = O*alpha + P @ V
        #pragma unroll
        for (int dt = 0; dt < 8; dt++) {
            o[dt][0] *= al0; o[dt][1] *= al0;
            o[dt][2] *= al1; o[dt][3] *= al1;
        }
        #pragma unroll
        for (int kc = 0; kc < 8; kc++) {
            unsigned a[4] = { PT(pr + g,     kc * 8 + t),
                              PT(pr + g + 8, kc * 8 + t),
                              PT(pr + g,     kc * 8 + t + 4),
                              PT(pr + g + 8, kc * 8 + t + 4) };
            #pragma unroll
            for (int dt = 0; dt < 8; dt++) {
                unsigned bb[2] = { VT(bf, kc * 8 + t,     dt * 8 + g),
                                   VT(bf, kc * 8 + t + 4, dt * 8 + g) };
                mma8(o[dt], a, bb);
            }
        }
        __syncthreads();  // all reads of buffer bf done before next stage into it
    }

    // Normalize and write ctx in [B, S, NH*HD] layout.
    const float i0 = 1.0f / lr0, i1 = 1.0f / lr1;
    #pragma unroll
    for (int dt = 0; dt < 8; dt++) {
        size_t base = (size_t)(b * S_ + q0 + g) * H_ + h * HD_ + dt * 8 + 2 * t;
        *(float2*)&out[base] = make_float2(o[dt][0] * i0, o[dt][1] * i0);
        *(float2*)&out[base + 8 * (size_t)H_] =
            make_float2(o[dt][2] * i1, o[dt][3] * i1);
    }
#undef KT
#undef VT
#undef PT
}

// ---------------------------------------------------------------------------
extern "C" void kernel_launch(void* const* d_in, const int* in_sizes, int n_in,
                              void* d_out, int out_size)
{
    const float* hs   = (const float*)d_in[0];
    const float* mask = (const float*)d_in[1];
    const float* Wq   = (const float*)d_in[2];
    const float* bq   = (const float*)d_in[3];
    const float* Wk   = (const float*)d_in[4];
    const float* bk   = (const float*)d_in[5];
    const float* Wv   = (const float*)d_in[6];
    const float* bv   = (const float*)d_in[7];
    const float* qe   = (const float*)d_in[8];
    const float* ke   = (const float*)d_in[9];
    const float* ve   = (const float*)d_in[10];
    const int*   idx  = (const int*)d_in[11];

    cudaFuncSetAttribute(qkv_proj, cudaFuncAttributeMaxDynamicSharedMemorySize,
                         QKV_SMEM);
    cudaFuncSetAttribute(flash_attn, cudaFuncAttributeMaxDynamicSharedMemorySize,
                         FL_SMEM);

    dim3 g1(24, 64);  // 24 n-blocks (3*1024/128) x 64 m-blocks (8192/128)
    qkv_proj<<<g1, 256, QKV_SMEM>>>(hs, Wq, bq, Wk, bk, Wv, bv, qe, ke, ve, idx);

    dim3 g2(S_ / 128, B_ * NH_);  // 16 q-tiles x 64 (b,h)
    flash_attn<<<g2, 256, FL_SMEM>>>(mask, (float*)d_out);
}

// round 7
// speedup vs baseline: 2.9423x; 1.8516x over previous
#include <cuda_runtime.h>
#include <cuda_fp16.h>
#include <cstdint>
#include <math.h>

#define B_  4
#define S_  2048
#define H_  1024
#define NH_ 16
#define HD_ 64

// f16 scratch.
__device__ __half g_hs[8192 * 1024];          // hidden, f16 [8192][1024]
__device__ __half g_wt[3][1024 * 1024];       // W^T f16 [n][k] for Q,K,V
__device__ __half g_qh[64 * 2048 * 64];       // Q f16 [bh][s][d], pre-scaled 1/8
__device__ __half g_kh[64 * 2048 * 64];       // K f16 [bh][s][d]
__device__ __half g_vt[64 * 64 * 2048];       // V^T f16 [bh][d][s]

__device__ __forceinline__ void mma16(float* c, const unsigned* a, const unsigned* b) {
    asm volatile(
        "mma.sync.aligned.m16n8k16.row.col.f32.f16.f16.f32 "
        "{%0,%1,%2,%3}, {%4,%5,%6,%7}, {%8,%9}, {%0,%1,%2,%3};\n"
        : "+f"(c[0]), "+f"(c[1]), "+f"(c[2]), "+f"(c[3])
        : "r"(a[0]), "r"(a[1]), "r"(a[2]), "r"(a[3]), "r"(b[0]), "r"(b[1]));
}

__device__ __forceinline__ void cpa16(void* dst, const void* src) {
    unsigned d = (unsigned)__cvta_generic_to_shared(dst);
    asm volatile("cp.async.cg.shared.global [%0], [%1], 16;\n" :: "r"(d), "l"(src));
}
#define CP_COMMIT asm volatile("cp.async.commit_group;\n" ::: "memory")
#define CP_WAIT1  asm volatile("cp.async.wait_group 1;\n" ::: "memory")

__device__ __forceinline__ unsigned h2u(float x, float y) {
    __half2 h = __floats2half2_rn(x, y);   // .x = low = first arg
    return *reinterpret_cast<unsigned*>(&h);
}

// ---------------------------------------------------------------------------
// Prep 1: hidden f32 -> f16.
// ---------------------------------------------------------------------------
__global__ __launch_bounds__(256) void cvt_hs(const float* __restrict__ hs) {
    int i = blockIdx.x * 256 + threadIdx.x;        // 2M threads, 4 elems each
    float4 v = ((const float4*)hs)[i];
    ((uint2*)g_hs)[i] = make_uint2(h2u(v.x, v.y), h2u(v.z, v.w));
}

// ---------------------------------------------------------------------------
// Prep 2: W -> W^T f16 (tiled transpose). grid (32,32,3), block (32,8).
// ---------------------------------------------------------------------------
__global__ __launch_bounds__(256) void cvt_wt(
    const float* __restrict__ Wq, const float* __restrict__ Wk,
    const float* __restrict__ Wv)
{
    __shared__ float t[32][33];
    const float* W = blockIdx.z == 0 ? Wq : (blockIdx.z == 1 ? Wk : Wv);
    __half* wt = g_wt[blockIdx.z];
    int tx = threadIdx.x, ty = threadIdx.y;
    int n0 = blockIdx.x * 32, k0 = blockIdx.y * 32;
    #pragma unroll
    for (int j = 0; j < 4; j++)
        t[ty + 8 * j][tx] = W[(size_t)(k0 + ty + 8 * j) * H_ + n0 + tx];
    __syncthreads();
    #pragma unroll
    for (int j = 0; j < 4; j++)
        wt[(size_t)(n0 + ty + 8 * j) * H_ + k0 + tx] =
            __float2half(t[tx][ty + 8 * j]);
}

// ---------------------------------------------------------------------------
// Kernel 1: fused QKV projection, f16 mma m16n8k16, cp.async double-buffered.
//   BM=128, BN=128, BK=32. 8 warps (4m x 2n), warp tile 32x64.
// ---------------------------------------------------------------------------
#define TS 20   // tile row stride in 32-bit words (16 data + 4 pad); 20%32=20
#define QKV_SMEM ((2 * 128 * TS + 2 * 128 * TS) * 4)

__global__ __launch_bounds__(256, 2) void qkv_proj(
    const float* __restrict__ bq, const float* __restrict__ bk,
    const float* __restrict__ bv,
    const float* __restrict__ qe, const float* __restrict__ ke,
    const float* __restrict__ ve,
    const int* __restrict__ indexp)
{
    extern __shared__ unsigned qsm[];
    unsigned* AsW = qsm;                  // [2][128][TS]
    unsigned* BsW = qsm + 2 * 128 * TS;   // [2][128][TS]
#define AT(bf,r,w) AsW[(bf)*128*TS + (r)*TS + (w)]
#define BT(bf,r,w) BsW[(bf)*128*TS + (r)*TS + (w)]

    const int tid  = threadIdx.x;
    const int lane = tid & 31;
    const int wid  = tid >> 5;
    const int g    = lane >> 2;
    const int t    = lane & 3;
    const int wm   = wid & 3;
    const int wn   = wid >> 2;

    const int nb  = blockIdx.x;   // 0..23, 8 per matrix
    const int mb  = blockIdx.y;   // 0..63
    const int sel = nb >> 3;      // 0=Q, 1=K, 2=V

    const __half* wt  = g_wt[sel];
    const float* bias = sel == 0 ? bq : (sel == 1 ? bk : bv);
    const float* emb  = (sel == 0 ? qe : (sel == 1 ? ke : ve)) + indexp[0] * H_;
    const float sc    = sel == 0 ? 0.125f : 1.0f;

    const int colm = (nb & 7) * 128;
    const int row0 = mb * 128;

    float acc[2][8][4] = {};

    auto stage = [&](int kt, int bf) {
        #pragma unroll
        for (int i = 0; i < 2; i++) {
            int idx = tid + i * 256;
            int r = idx >> 2, ch = idx & 3;
            cpa16(&AT(bf, r, ch * 4), &g_hs[(size_t)(row0 + r) * H_ + kt + ch * 8]);
            cpa16(&BT(bf, r, ch * 4), &wt[(size_t)(colm + r) * H_ + kt + ch * 8]);
        }
    };

    stage(0, 0);
    CP_COMMIT;

    for (int it = 0; it < H_ / 32; it++) {
        const int bf = it & 1;
        if (it + 1 < H_ / 32) stage((it + 1) * 32, bf ^ 1);
        CP_COMMIT;
        CP_WAIT1;
        __syncthreads();

        #pragma unroll
        for (int kk = 0; kk < 2; kk++) {
            unsigned a[2][4];
            #pragma unroll
            for (int mt = 0; mt < 2; mt++) {
                int r = wm * 32 + mt * 16;
                a[mt][0] = AT(bf, r + g,     kk * 8 + t);
                a[mt][1] = AT(bf, r + g + 8, kk * 8 + t);
                a[mt][2] = AT(bf, r + g,     kk * 8 + t + 4);
                a[mt][3] = AT(bf, r + g + 8, kk * 8 + t + 4);
            }
            #pragma unroll
            for (int nt = 0; nt < 8; nt++) {
                int c = wn * 64 + nt * 8 + g;
                unsigned bb[2] = { BT(bf, c, kk * 8 + t),
                                   BT(bf, c, kk * 8 + t + 4) };
                mma16(acc[0][nt], a[0], bb);
                mma16(acc[1][nt], a[1], bb);
            }
        }
        __syncthreads();
    }

    // Epilogue: +bias+emb, (Q: *1/8), f16, scatter.
    #pragma unroll
    for (int nt = 0; nt < 8; nt++) {
        const int cm   = colm + wn * 64 + nt * 8 + 2 * t;
        const float b0 = bias[cm]     + emb[cm];
        const float b1 = bias[cm + 1] + emb[cm + 1];
        const int head = cm >> 6;
        const int d    = cm & 63;
        #pragma unroll
        for (int mt = 0; mt < 2; mt++) {
            int row = row0 + wm * 32 + mt * 16 + g;
            int bt  = row >> 11;
            int s   = row & 2047;
            int bh  = bt * NH_ + head;
            float x0 = (acc[mt][nt][0] + b0) * sc;
            float x1 = (acc[mt][nt][1] + b1) * sc;
            float x2 = (acc[mt][nt][2] + b0) * sc;
            float x3 = (acc[mt][nt][3] + b1) * sc;
            if (sel < 2) {
                __half* dst = (sel ? g_kh : g_qh)
                            + ((size_t)bh * S_ + s) * HD_ + d;
                *(unsigned*)dst             = h2u(x0, x1);
                *(unsigned*)(dst + 8 * HD_) = h2u(x2, x3);   // rows s, s+8
            } else {
                __half* dst = g_vt + (size_t)bh * HD_ * S_;
                dst[(size_t)d       * S_ + s]     = __float2half(x0);
                dst[(size_t)(d + 1) * S_ + s]     = __float2half(x1);
                dst[(size_t)d       * S_ + s + 8] = __float2half(x2);
                dst[(size_t)(d + 1) * S_ + s + 8] = __float2half(x3);
            }
        }
    }
#undef AT
#undef BT
}

// ---------------------------------------------------------------------------
// Kernel 2: flash attention, f16 mma, P kept in registers (no smem roundtrip).
//   Block = 128 q-rows x one (b,h). 8 warps x 16 q-rows. 64-key tiles.
// ---------------------------------------------------------------------------
#define FS 36   // K/V tile row stride in words (32 data + 4 pad); 36%32=4
#define FL_SMEM ((4 * 64 * FS + 2 * 64) * 4)

__global__ __launch_bounds__(256, 2) void flash_attn(
    const float* __restrict__ mask, float* __restrict__ out)
{
    extern __shared__ unsigned fsm[];
    unsigned* KsW = fsm;                  // [2][64 keys][FS]  (K: [s][d] f16)
    unsigned* VtW = fsm + 2 * 64 * FS;    // [2][64 dims][FS]  (V^T: [d][s] f16)
    float*    Ms  = (float*)(fsm + 4 * 64 * FS);  // [2][64]
#define KT(bf,r,w) KsW[(bf)*64*FS + (r)*FS + (w)]
#define VT(bf,r,w) VtW[(bf)*64*FS + (r)*FS + (w)]

    const int tid  = threadIdx.x;
    const int lane = tid & 31;
    const int wid  = tid >> 5;
    const int g    = lane >> 2;
    const int t    = lane & 3;

    const int bh = blockIdx.y;
    const int b  = bh >> 4, h = bh & 15;
    const __half* Qp  = g_qh + (size_t)bh * S_ * HD_;
    const __half* Kp  = g_kh + (size_t)bh * S_ * HD_;
    const __half* Vtp = g_vt + (size_t)bh * HD_ * S_;
    const float* maskp = mask + b * S_;
    const int q0 = blockIdx.x * 128 + wid * 16;

    auto stage = [&](int kt, int bf) {
        #pragma unroll
        for (int i = 0; i < 2; i++) {
            int idx = tid + i * 256;
            int r = idx >> 3, ch = idx & 7;
            cpa16(&KT(bf, r, ch * 4), &Kp[(size_t)(kt + r) * HD_ + ch * 8]);
            cpa16(&VT(bf, r, ch * 4), &Vtp[(size_t)r * S_ + kt + ch * 8]);
        }
        if (tid < 16) cpa16(&Ms[bf * 64 + tid * 4], &maskp[kt + tid * 4]);
    };

    // Q A-fragments (f16 pairs, pre-scaled), resident for the whole block.
    unsigned qa[4][4];
    {
        const __half* q0p = Qp + (size_t)(q0 + g) * HD_;
        const __half* q8p = q0p + 8 * HD_;
        #pragma unroll
        for (int dc = 0; dc < 4; dc++) {
            qa[dc][0] = *(const unsigned*)(q0p + dc * 16 + 2 * t);
            qa[dc][1] = *(const unsigned*)(q8p + dc * 16 + 2 * t);
            qa[dc][2] = *(const unsigned*)(q0p + dc * 16 + 2 * t + 8);
            qa[dc][3] = *(const unsigned*)(q8p + dc * 16 + 2 * t + 8);
        }
    }

    float o[8][4] = {};
    float mr0 = -1e30f, mr1 = -1e30f, lr0 = 0.f, lr1 = 0.f;

    stage(0, 0);
    CP_COMMIT;

    for (int it = 0; it < S_ / 64; it++) {
        const int bf = it & 1;
        if (it + 1 < S_ / 64) stage((it + 1) * 64, bf ^ 1);
        CP_COMMIT;
        CP_WAIT1;
        __syncthreads();

        // S = Q @ K^T   (A=Q rows, B=K [d][key] via contiguous dim-pairs)
        float s[8][4] = {};
        #pragma unroll
        for (int dc = 0; dc < 4; dc++) {
            #pragma unroll
            for (int nt = 0; nt < 8; nt++) {
                unsigned bb[2] = { KT(bf, nt * 8 + g, dc * 8 + t),
                                   KT(bf, nt * 8 + g, dc * 8 + t + 4) };
                mma16(s[nt], qa[dc], bb);
            }
        }

        // mask + row max
        float r0 = -1e30f, r1 = -1e30f;
        #pragma unroll
        for (int nt = 0; nt < 8; nt++) {
            float m0 = Ms[bf * 64 + nt * 8 + 2 * t];
            float m1 = Ms[bf * 64 + nt * 8 + 2 * t + 1];
            s[nt][0] += m0; s[nt][1] += m1; s[nt][2] += m0; s[nt][3] += m1;
            r0 = fmaxf(r0, fmaxf(s[nt][0], s[nt][1]));
            r1 = fmaxf(r1, fmaxf(s[nt][2], s[nt][3]));
        }
        r0 = fmaxf(r0, __shfl_xor_sync(0xffffffffu, r0, 1));
        r0 = fmaxf(r0, __shfl_xor_sync(0xffffffffu, r0, 2));
        r1 = fmaxf(r1, __shfl_xor_sync(0xffffffffu, r1, 1));
        r1 = fmaxf(r1, __shfl_xor_sync(0xffffffffu, r1, 2));

        float mn0 = fmaxf(mr0, r0), mn1 = fmaxf(mr1, r1);
        float al0 = __expf(mr0 - mn0), al1 = __expf(mr1 - mn1);
        mr0 = mn0; mr1 = mn1;

        // P = exp(S - m), row sums
        float ps0 = 0.f, ps1 = 0.f;
        #pragma unroll
        for (int nt = 0; nt < 8; nt++) {
            s[nt][0] = __expf(s[nt][0] - mn0);
            s[nt][1] = __expf(s[nt][1] - mn0);
            s[nt][2] = __expf(s[nt][2] - mn1);
            s[nt][3] = __expf(s[nt][3] - mn1);
            ps0 += s[nt][0] + s[nt][1];
            ps1 += s[nt][2] + s[nt][3];
        }
        ps0 += __shfl_xor_sync(0xffffffffu, ps0, 1);
        ps0 += __shfl_xor_sync(0xffffffffu, ps0, 2);
        ps1 += __shfl_xor_sync(0xffffffffu, ps1, 1);
        ps1 += __shfl_xor_sync(0xffffffffu, ps1, 2);
        lr0 = lr0 * al0 + ps0;
        lr1 = lr1 * al1 + ps1;

        // O = O*alpha + P @ V ; P packed straight from C-frags into A-frags.
        #pragma unroll
        for (int dt = 0; dt < 8; dt++) {
            o[dt][0] *= al0; o[dt][1] *= al0;
            o[dt][2] *= al1; o[dt][3] *= al1;
        }
        #pragma unroll
        for (int kc = 0; kc < 4; kc++) {
            unsigned a[4] = { h2u(s[2*kc][0],   s[2*kc][1]),
                              h2u(s[2*kc][2],   s[2*kc][3]),
                              h2u(s[2*kc+1][0], s[2*kc+1][1]),
                              h2u(s[2*kc+1][2], s[2*kc+1][3]) };
            #pragma unroll
            for (int dt = 0; dt < 8; dt++) {
                unsigned bb[2] = { VT(bf, dt * 8 + g, kc * 8 + t),
                                   VT(bf, dt * 8 + g, kc * 8 + t + 4) };
                mma16(o[dt], a, bb);
            }
        }
        __syncthreads();  // all reads of buffer bf done before restaging into it
    }

    // Normalize and write ctx [B, S, NH*HD] f32.
    const float i0 = 1.0f / lr0, i1 = 1.0f / lr1;
    #pragma unroll
    for (int dt = 0; dt < 8; dt++) {
        size_t base = (size_t)(b * S_ + q0 + g) * H_ + h * HD_ + dt * 8 + 2 * t;
        *(float2*)&out[base] = make_float2(o[dt][0] * i0, o[dt][1] * i0);
        *(float2*)&out[base + 8 * (size_t)H_] =
            make_float2(o[dt][2] * i1, o[dt][3] * i1);
    }
#undef KT
#undef VT
}

// ---------------------------------------------------------------------------
extern "C" void kernel_launch(void* const* d_in, const int* in_sizes, int n_in,
                              void* d_out, int out_size)
{
    const float* hs   = (const float*)d_in[0];
    const float* mask = (const float*)d_in[1];
    const float* Wq   = (const float*)d_in[2];
    const float* bq   = (const float*)d_in[3];
    const float* Wk   = (const float*)d_in[4];
    const float* bk   = (const float*)d_in[5];
    const float* Wv   = (const float*)d_in[6];
    const float* bv   = (const float*)d_in[7];
    const float* qe   = (const float*)d_in[8];
    const float* ke   = (const float*)d_in[9];
    const float* ve   = (const float*)d_in[10];
    const int*   idx  = (const int*)d_in[11];

    cudaFuncSetAttribute(qkv_proj, cudaFuncAttributeMaxDynamicSharedMemorySize,
                         QKV_SMEM);
    cudaFuncSetAttribute(flash_attn, cudaFuncAttributeMaxDynamicSharedMemorySize,
                         FL_SMEM);

    cvt_hs<<<8192, 256>>>(hs);                       // 8M f32 -> f16
    cvt_wt<<<dim3(32, 32, 3), dim3(32, 8)>>>(Wq, Wk, Wv);

    dim3 g1(24, 64);
    qkv_proj<<<g1, 256, QKV_SMEM>>>(bq, bk, bv, qe, ke, ve, idx);

    dim3 g2(S_ / 128, B_ * NH_);
    flash_attn<<<g2, 256, FL_SMEM>>>(mask, (float*)d_out);
}